// round 6
// baseline (speedup 1.0000x reference)
#include <cuda_runtime.h>
#include <math.h>

#define G 384
#define WORDS 6            // 384 bits / 64
#define NLINES (G * G)     // (x,y) lines

typedef unsigned long long u64;

// bit-packed occupancy grid and dilated grid (7 MB each)
__device__ u64 g_bits[NLINES * WORDS];
__device__ u64 g_dil [NLINES * WORDS];

// ---------------------------------------------------------------------------
// K0: clear the bit grid
// ---------------------------------------------------------------------------
__global__ void clear_bits_kernel() {
    int i = blockIdx.x * blockDim.x + threadIdx.x;
    if (i < NLINES * WORDS) g_bits[i] = 0ull;
}

// ---------------------------------------------------------------------------
// K1: gaussian smooth (eager-XLA semantics: plain fp32 mul/add, each op
//     rounded; no FMA contraction) + scatter bits.
//     Index: XLA rewrites x / const -> x * (1/const); fl32(1/fl32(1/384))
//     is exactly 384.0f, so the reference scales by multiplication.
// ---------------------------------------------------------------------------
__device__ __forceinline__ int reflect_idx(int j, int n) {
    // numpy 'symmetric' padding: -1->0, -2->1, n->n-1, n+1->n-2
    if (j < 0)  return -j - 1;
    if (j >= n) return 2 * n - 1 - j;
    return j;
}

// 5-term chain, left-associated, every op individually rounded (no FMA):
// s = ((((u0*t0 + u1*t1) + u2*t2) + u3*t3) + u4*t4)
__device__ __forceinline__ float chain5(float u0, float t0, float u1, float t1,
                                        float u2, float t2, float u3, float t3,
                                        float u4, float t4) {
    float s = __fmul_rn(u0, t0);
    s = __fadd_rn(s, __fmul_rn(u1, t1));
    s = __fadd_rn(s, __fmul_rn(u2, t2));
    s = __fadd_rn(s, __fmul_rn(u3, t3));
    s = __fadd_rn(s, __fmul_rn(u4, t4));
    return s;
}

__global__ void smooth_scatter_kernel(const float* __restrict__ pts, int n,
                                      float w0, float w1, float w2) {
    int j = blockIdx.x * blockDim.x + threadIdx.x;
    if (j >= n) return;

    int jm2 = reflect_idx(j - 2, n);
    int jm1 = reflect_idx(j - 1, n);
    int jp1 = reflect_idx(j + 1, n);
    int jp2 = reflect_idx(j + 2, n);

    float y[3];
#pragma unroll
    for (int c = 0; c < 3; c++) {
        float a = __ldg(&pts[jm2 * 3 + c]);
        float b = __ldg(&pts[jm1 * 3 + c]);
        float d = __ldg(&pts[j   * 3 + c]);
        float e = __ldg(&pts[jp1 * 3 + c]);
        float f = __ldg(&pts[jp2 * 3 + c]);
        // reference terms in order: (w0,a),(w1,b),(w2,d),(w1,e),(w0,f)
        y[c] = chain5(w0, a, w1, b, w2, d, w1, e, w0, f);
    }

    // axis-1 smoothing, symmetric pad of [y0,y1,y2] -> [y1,y0 | y0,y1,y2 | y2,y1]
    float z0 = chain5(w0, y[1], w1, y[0], w2, y[0], w1, y[1], w0, y[2]);
    float z1 = chain5(w0, y[0], w1, y[0], w2, y[1], w1, y[2], w0, y[2]);
    float z2 = chain5(w0, y[0], w1, y[1], w2, y[2], w1, y[2], w0, y[1]);

    // XLA: divide-by-constant -> multiply-by-reciprocal; fl32(1/vox) == 384.0f
    int ix = (int)floorf(__fmul_rn(z0, 384.0f));
    int iy = (int)floorf(__fmul_rn(z1, 384.0f));
    int iz = (int)floorf(__fmul_rn(z2, 384.0f));
    ix = min(max(ix, 0), G - 1);
    iy = min(max(iy, 0), G - 1);
    iz = min(max(iz, 0), G - 1);

    atomicOr(&g_bits[(ix * G + iy) * WORDS + (iz >> 6)], 1ull << (iz & 63));
}

// ---------------------------------------------------------------------------
// K2: 3x3x3 binary dilation (bit-packed). One thread per (x,y) line.
// ---------------------------------------------------------------------------
__global__ void dilate_kernel() {
    int line = blockIdx.x * blockDim.x + threadIdx.x;
    if (line >= NLINES) return;
    int x = line / G;
    int y = line - x * G;

    u64 acc[WORDS];
#pragma unroll
    for (int k = 0; k < WORDS; k++) acc[k] = 0ull;

#pragma unroll
    for (int dx = -1; dx <= 1; dx++) {
        int xx = x + dx;
        if (xx < 0 || xx >= G) continue;
#pragma unroll
        for (int dy = -1; dy <= 1; dy++) {
            int yy = y + dy;
            if (yy < 0 || yy >= G) continue;
            const u64* L = &g_bits[(xx * G + yy) * WORDS];
            u64 prev = 0ull;
            u64 cur  = __ldg(&L[0]);
#pragma unroll
            for (int k = 0; k < WORDS; k++) {
                u64 nxt = (k < WORDS - 1) ? __ldg(&L[k + 1]) : 0ull;
                u64 sl = (cur << 1) | (prev >> 63);  // bit z gets z-1
                u64 sr = (cur >> 1) | (nxt << 63);   // bit z gets z+1
                acc[k] |= cur | sl | sr;
                prev = cur;
                cur = nxt;
            }
        }
    }

    u64* D = &g_dil[line * WORDS];
#pragma unroll
    for (int k = 0; k < WORDS; k++) D[k] = acc[k];
}

// ---------------------------------------------------------------------------
// K3: 3x3x3 binary erosion of the dilated grid + expand to fp32 output.
// Each block handles 4 consecutive lines; coalesced float4 stores.
// ---------------------------------------------------------------------------
__global__ void erode_expand_kernel(float* __restrict__ out) {
    __shared__ u64 sw[4][WORDS];
    int base = blockIdx.x * 4;
    int t = threadIdx.x;  // 0..383

    if (t < 4 * WORDS) {
        int l = t / WORDS;
        int k = t - l * WORDS;
        int line = base + l;
        int x = line / G;
        int y = line - x * G;

        u64 r;
        if (x == 0 || x == G - 1 || y == 0 || y == G - 1) {
            // zero-pad: erosion at grid border is 0
            r = 0ull;
        } else {
            r = ~0ull;
#pragma unroll
            for (int dx = -1; dx <= 1; dx++) {
#pragma unroll
                for (int dy = -1; dy <= 1; dy++) {
                    const u64* L = &g_dil[((x + dx) * G + (y + dy)) * WORDS];
                    u64 cur  = __ldg(&L[k]);
                    u64 prev = (k > 0)         ? __ldg(&L[k - 1]) : 0ull;
                    u64 nxt  = (k < WORDS - 1) ? __ldg(&L[k + 1]) : 0ull;
                    u64 sl = (cur << 1) | (prev >> 63);
                    u64 sr = (cur >> 1) | (nxt << 63);
                    r &= cur & sl & sr;
                }
            }
        }
        sw[l][k] = r;
    }
    __syncthreads();

    // 384 threads: 96 threads per line, each writes one float4 (4 z-values)
    int l = t / 96;              // line within block
    int q = t - l * 96;          // float4 index within line
    int line = base + l;
    int z = q * 4;

    float4 v;
    u64 w = sw[l][z >> 6];
    int b = z & 63;
    v.x = (float)((w >> (b + 0)) & 1ull);
    v.y = (float)((w >> (b + 1)) & 1ull);
    v.z = (float)((w >> (b + 2)) & 1ull);
    v.w = (float)((w >> (b + 3)) & 1ull);

    reinterpret_cast<float4*>(out)[line * (G / 4) + q] = v;
}

// ---------------------------------------------------------------------------
// launch
// ---------------------------------------------------------------------------
extern "C" void kernel_launch(void* const* d_in, const int* in_sizes, int n_in,
                              void* d_out, int out_size) {
    const float* pts = (const float*)d_in[0];
    int n = in_sizes[0] / 3;
    float* out = (float*)d_out;

    // gaussian weights, replicating numpy fp32 arithmetic:
    // w = exp(-0.5*(t/0.5)^2) for t=-2..2 -> [e^-8, e^-2, 1, e^-2, e^-8] (fp32)
    // normalized by sequential fp32 sum (numpy n<8 path), fp32 division.
    float e8 = (float)exp(-8.0);   // correctly-rounded fp32 of exp(-8)
    float e2 = (float)exp(-2.0);   // correctly-rounded fp32 of exp(-2)
    float s = e8;
    s = s + e2;
    s = s + 1.0f;
    s = s + e2;
    s = s + e8;
    float w0 = e8 / s;
    float w1 = e2 / s;
    float w2 = 1.0f / s;

    clear_bits_kernel<<<(NLINES * WORDS + 511) / 512, 512>>>();
    smooth_scatter_kernel<<<(n + 255) / 256, 256>>>(pts, n, w0, w1, w2);
    dilate_kernel<<<(NLINES + 127) / 128, 128>>>();
    erode_expand_kernel<<<NLINES / 4, 384>>>(out);
}

// round 8
// speedup vs baseline: 3.1449x; 3.1449x over previous
#include <cuda_runtime.h>
#include <math.h>

#define G 384
#define WORDS 6            // 384 bits / 64
#define NLINES (G * G)     // (x,y) lines

typedef unsigned long long u64;

// bit-packed occupancy, dilated, eroded grids (7 MB each; L2-resident)
__device__ u64 g_bits[NLINES * WORDS];
__device__ u64 g_dil [NLINES * WORDS];
__device__ u64 g_ero [NLINES * WORDS];

// ---------------------------------------------------------------------------
// K0: clear the bit grid
// ---------------------------------------------------------------------------
__global__ void clear_bits_kernel() {
    int i = blockIdx.x * blockDim.x + threadIdx.x;
    if (i < NLINES * WORDS) g_bits[i] = 0ull;
}

// ---------------------------------------------------------------------------
// K1: gaussian smooth (eager-XLA semantics: plain fp32 mul/add, each op
//     rounded; no FMA contraction) + scatter bits.
//     Index: XLA rewrites x / const -> x * (1/const); fl32(1/fl32(1/384))
//     is exactly 384.0f, so the reference scales by multiplication.
// ---------------------------------------------------------------------------
__device__ __forceinline__ int reflect_idx(int j, int n) {
    // numpy 'symmetric' padding: -1->0, -2->1, n->n-1, n+1->n-2
    if (j < 0)  return -j - 1;
    if (j >= n) return 2 * n - 1 - j;
    return j;
}

// 5-term chain, left-associated, every op individually rounded (no FMA)
__device__ __forceinline__ float chain5(float u0, float t0, float u1, float t1,
                                        float u2, float t2, float u3, float t3,
                                        float u4, float t4) {
    float s = __fmul_rn(u0, t0);
    s = __fadd_rn(s, __fmul_rn(u1, t1));
    s = __fadd_rn(s, __fmul_rn(u2, t2));
    s = __fadd_rn(s, __fmul_rn(u3, t3));
    s = __fadd_rn(s, __fmul_rn(u4, t4));
    return s;
}

__global__ void smooth_scatter_kernel(const float* __restrict__ pts, int n,
                                      float w0, float w1, float w2) {
    int j = blockIdx.x * blockDim.x + threadIdx.x;
    if (j >= n) return;

    int jm2 = reflect_idx(j - 2, n);
    int jm1 = reflect_idx(j - 1, n);
    int jp1 = reflect_idx(j + 1, n);
    int jp2 = reflect_idx(j + 2, n);

    float y[3];
#pragma unroll
    for (int c = 0; c < 3; c++) {
        float a = __ldg(&pts[jm2 * 3 + c]);
        float b = __ldg(&pts[jm1 * 3 + c]);
        float d = __ldg(&pts[j   * 3 + c]);
        float e = __ldg(&pts[jp1 * 3 + c]);
        float f = __ldg(&pts[jp2 * 3 + c]);
        y[c] = chain5(w0, a, w1, b, w2, d, w1, e, w0, f);
    }

    // axis-1 smoothing, symmetric pad of [y0,y1,y2] -> [y1,y0 | y0,y1,y2 | y2,y1]
    float z0 = chain5(w0, y[1], w1, y[0], w2, y[0], w1, y[1], w0, y[2]);
    float z1 = chain5(w0, y[0], w1, y[0], w2, y[1], w1, y[2], w0, y[2]);
    float z2 = chain5(w0, y[0], w1, y[1], w2, y[2], w1, y[2], w0, y[1]);

    int ix = (int)floorf(__fmul_rn(z0, 384.0f));
    int iy = (int)floorf(__fmul_rn(z1, 384.0f));
    int iz = (int)floorf(__fmul_rn(z2, 384.0f));
    ix = min(max(ix, 0), G - 1);
    iy = min(max(iy, 0), G - 1);
    iz = min(max(iz, 0), G - 1);

    atomicOr(&g_bits[(ix * G + iy) * WORDS + (iz >> 6)], 1ull << (iz & 63));
}

// ---------------------------------------------------------------------------
// K2: 3x3x3 binary dilation (bit-packed). One thread per (x,y) line.
// ---------------------------------------------------------------------------
__global__ void dilate_kernel() {
    int line = blockIdx.x * blockDim.x + threadIdx.x;
    if (line >= NLINES) return;
    int x = line / G;
    int y = line - x * G;

    u64 acc[WORDS];
#pragma unroll
    for (int k = 0; k < WORDS; k++) acc[k] = 0ull;

#pragma unroll
    for (int dx = -1; dx <= 1; dx++) {
        int xx = x + dx;
        if (xx < 0 || xx >= G) continue;
#pragma unroll
        for (int dy = -1; dy <= 1; dy++) {
            int yy = y + dy;
            if (yy < 0 || yy >= G) continue;
            const u64* L = &g_bits[(xx * G + yy) * WORDS];
            u64 prev = 0ull;
            u64 cur  = __ldg(&L[0]);
#pragma unroll
            for (int k = 0; k < WORDS; k++) {
                u64 nxt = (k < WORDS - 1) ? __ldg(&L[k + 1]) : 0ull;
                u64 sl = (cur << 1) | (prev >> 63);  // bit z gets z-1
                u64 sr = (cur >> 1) | (nxt << 63);   // bit z gets z+1
                acc[k] |= cur | sl | sr;
                prev = cur;
                cur = nxt;
            }
        }
    }

    u64* D = &g_dil[line * WORDS];
#pragma unroll
    for (int k = 0; k < WORDS; k++) D[k] = acc[k];
}

// ---------------------------------------------------------------------------
// K3: 3x3x3 binary erosion (bit-packed). One thread per (x,y) line.
// Zero-pad semantics: border lines erode to 0; z-borders handled by the
// zero carries (prev=0 at k=0, nxt=0 at k=WORDS-1).
// ---------------------------------------------------------------------------
__global__ void erode_kernel() {
    int line = blockIdx.x * blockDim.x + threadIdx.x;
    if (line >= NLINES) return;
    int x = line / G;
    int y = line - x * G;

    u64* E = &g_ero[line * WORDS];

    if (x == 0 || x == G - 1 || y == 0 || y == G - 1) {
#pragma unroll
        for (int k = 0; k < WORDS; k++) E[k] = 0ull;
        return;
    }

    u64 acc[WORDS];
#pragma unroll
    for (int k = 0; k < WORDS; k++) acc[k] = ~0ull;

#pragma unroll
    for (int dx = -1; dx <= 1; dx++) {
#pragma unroll
        for (int dy = -1; dy <= 1; dy++) {
            const u64* L = &g_dil[((x + dx) * G + (y + dy)) * WORDS];
            u64 prev = 0ull;
            u64 cur  = __ldg(&L[0]);
#pragma unroll
            for (int k = 0; k < WORDS; k++) {
                u64 nxt = (k < WORDS - 1) ? __ldg(&L[k + 1]) : 0ull;
                u64 sl = (cur << 1) | (prev >> 63);
                u64 sr = (cur >> 1) | (nxt << 63);
                acc[k] &= cur & sl & sr;
                prev = cur;
                cur = nxt;
            }
        }
    }

#pragma unroll
    for (int k = 0; k < WORDS; k++) E[k] = acc[k];
}

// ---------------------------------------------------------------------------
// K4: streaming expand bits -> fp32. Fully coalesced float4 stores:
// consecutive threads write consecutive float4s; each thread does
// EXP_ITERS iterations at +blockDim stride (keeps every STG.128 warp-dense).
// ---------------------------------------------------------------------------
#define EXP_THREADS 256
#define EXP_ITERS 4
// total float4s = G^3/4 = 14,155,776 = 13824 blocks * 256 threads * 4 iters

__global__ void expand_kernel(float* __restrict__ out) {
    const unsigned int* __restrict__ bits32 = (const unsigned int*)g_ero;
    int base = blockIdx.x * (EXP_THREADS * EXP_ITERS) + threadIdx.x;
#pragma unroll
    for (int j = 0; j < EXP_ITERS; j++) {
        int idx = base + j * EXP_THREADS;        // float4 index (4 z-bits)
        unsigned int w = __ldg(&bits32[idx >> 3]);
        int sh = (idx & 7) * 4;
        float4 v;
        v.x = (float)((w >> (sh + 0)) & 1u);
        v.y = (float)((w >> (sh + 1)) & 1u);
        v.z = (float)((w >> (sh + 2)) & 1u);
        v.w = (float)((w >> (sh + 3)) & 1u);
        reinterpret_cast<float4*>(out)[idx] = v;
    }
}

// ---------------------------------------------------------------------------
// launch
// ---------------------------------------------------------------------------
extern "C" void kernel_launch(void* const* d_in, const int* in_sizes, int n_in,
                              void* d_out, int out_size) {
    const float* pts = (const float*)d_in[0];
    int n = in_sizes[0] / 3;
    float* out = (float*)d_out;

    // gaussian weights (fp32, numpy semantics): [e^-8, e^-2, 1, e^-2, e^-8]/sum
    float e8 = (float)exp(-8.0);
    float e2 = (float)exp(-2.0);
    float s = e8;
    s = s + e2;
    s = s + 1.0f;
    s = s + e2;
    s = s + e8;
    float w0 = e8 / s;
    float w1 = e2 / s;
    float w2 = 1.0f / s;

    clear_bits_kernel<<<(NLINES * WORDS + 511) / 512, 512>>>();
    smooth_scatter_kernel<<<(n + 255) / 256, 256>>>(pts, n, w0, w1, w2);
    dilate_kernel<<<(NLINES + 127) / 128, 128>>>();
    erode_kernel<<<(NLINES + 127) / 128, 128>>>();
    int nf4 = (G * G * G) / 4;
    expand_kernel<<<nf4 / (EXP_THREADS * EXP_ITERS), EXP_THREADS>>>(out);
}

// round 9
// speedup vs baseline: 3.8013x; 1.2087x over previous
#include <cuda_runtime.h>
#include <math.h>

#define G 384
#define WORDS 6            // 384 bits / 64
#define NLINES (G * G)     // (x,y) lines
#define TS 16              // tile size (output lines per axis per block)
#define NT (G / TS)        // 24 tiles per axis

typedef unsigned long long u64;

// bit-packed occupancy grid (7 MB; L2-resident)
__device__ u64 g_bits[NLINES * WORDS];

// ---------------------------------------------------------------------------
// K0: clear the bit grid
// ---------------------------------------------------------------------------
__global__ void clear_bits_kernel() {
    int i = blockIdx.x * blockDim.x + threadIdx.x;
    if (i < NLINES * WORDS) g_bits[i] = 0ull;
}

// ---------------------------------------------------------------------------
// K1: gaussian smooth (eager-XLA semantics: plain fp32 mul/add, each op
//     rounded; no FMA contraction) + scatter bits.
//     Index: XLA rewrites x / const -> x * (1/const); fl32(1/fl32(1/384))
//     is exactly 384.0f, so the reference scales by multiplication.
// ---------------------------------------------------------------------------
__device__ __forceinline__ int reflect_idx(int j, int n) {
    // numpy 'symmetric' padding: -1->0, -2->1, n->n-1, n+1->n-2
    if (j < 0)  return -j - 1;
    if (j >= n) return 2 * n - 1 - j;
    return j;
}

// 5-term chain, left-associated, every op individually rounded (no FMA)
__device__ __forceinline__ float chain5(float u0, float t0, float u1, float t1,
                                        float u2, float t2, float u3, float t3,
                                        float u4, float t4) {
    float s = __fmul_rn(u0, t0);
    s = __fadd_rn(s, __fmul_rn(u1, t1));
    s = __fadd_rn(s, __fmul_rn(u2, t2));
    s = __fadd_rn(s, __fmul_rn(u3, t3));
    s = __fadd_rn(s, __fmul_rn(u4, t4));
    return s;
}

__global__ void smooth_scatter_kernel(const float* __restrict__ pts, int n,
                                      float w0, float w1, float w2) {
    int j = blockIdx.x * blockDim.x + threadIdx.x;
    if (j >= n) return;

    int jm2 = reflect_idx(j - 2, n);
    int jm1 = reflect_idx(j - 1, n);
    int jp1 = reflect_idx(j + 1, n);
    int jp2 = reflect_idx(j + 2, n);

    float y[3];
#pragma unroll
    for (int c = 0; c < 3; c++) {
        float a = __ldg(&pts[jm2 * 3 + c]);
        float b = __ldg(&pts[jm1 * 3 + c]);
        float d = __ldg(&pts[j   * 3 + c]);
        float e = __ldg(&pts[jp1 * 3 + c]);
        float f = __ldg(&pts[jp2 * 3 + c]);
        y[c] = chain5(w0, a, w1, b, w2, d, w1, e, w0, f);
    }

    // axis-1 smoothing, symmetric pad of [y0,y1,y2] -> [y1,y0 | y0,y1,y2 | y2,y1]
    float z0 = chain5(w0, y[1], w1, y[0], w2, y[0], w1, y[1], w0, y[2]);
    float z1 = chain5(w0, y[0], w1, y[0], w2, y[1], w1, y[2], w0, y[2]);
    float z2 = chain5(w0, y[0], w1, y[1], w2, y[2], w1, y[2], w0, y[1]);

    int ix = (int)floorf(__fmul_rn(z0, 384.0f));
    int iy = (int)floorf(__fmul_rn(z1, 384.0f));
    int iz = (int)floorf(__fmul_rn(z2, 384.0f));
    ix = min(max(ix, 0), G - 1);
    iy = min(max(iy, 0), G - 1);
    iz = min(max(iz, 0), G - 1);

    atomicOr(&g_bits[(ix * G + iy) * WORDS + (iz >> 6)], 1ull << (iz & 63));
}

// ---------------------------------------------------------------------------
// K2: fused 3x3x3 closing (dilate -> erode) + fp32 expand, tiled in smem.
// Per block: 16x16 output lines. Halo: bits 20x20, dilated 18x18.
// OR/AND commute with the z bit-shifts, so each stage is:
//   combine 9 neighbor lines wordwise, then one z-shift triple.
// ---------------------------------------------------------------------------
__global__ void __launch_bounds__(256) close_expand_kernel(float* __restrict__ out) {
    __shared__ u64 sb[20][20][WORDS];   // bits halo      (19200 B)
    __shared__ u64 sd[18][18][WORDS];   // dilated        (15552 B)
    __shared__ u64 se[TS][TS][WORDS];   // eroded         (12288 B)

    int t = threadIdx.x;
    int X0 = (int)blockIdx.x * TS;      // tile origin x
    int Y0 = (int)blockIdx.y * TS;      // tile origin y

    // ---- phase 1: load 20x20 line halo of g_bits (zero OOB) ----
    for (int w = t; w < 20 * 20 * WORDS; w += 256) {
        int l  = w / WORDS;
        int k  = w - l * WORDS;
        int xx = l / 20;
        int yy = l - xx * 20;
        int ax = X0 - 2 + xx;
        int ay = Y0 - 2 + yy;
        u64 v = 0ull;
        if (ax >= 0 && ax < G && ay >= 0 && ay < G)
            v = g_bits[(ax * G + ay) * WORDS + k];
        sb[xx][yy][k] = v;
    }
    __syncthreads();

    // ---- phase 2: dilation for 18x18 interior ----
    for (int li = t; li < 18 * 18; li += 256) {
        int xx = li / 18;
        int yy = li - xx * 18;
        u64 o[WORDS];
#pragma unroll
        for (int k = 0; k < WORDS; k++) o[k] = 0ull;
#pragma unroll
        for (int dx = 0; dx < 3; dx++)
#pragma unroll
            for (int dy = 0; dy < 3; dy++) {
#pragma unroll
                for (int k = 0; k < WORDS; k++) o[k] |= sb[xx + dx][yy + dy][k];
            }
#pragma unroll
        for (int k = 0; k < WORDS; k++) {
            u64 prev = (k > 0)         ? o[k - 1] : 0ull;
            u64 nxt  = (k < WORDS - 1) ? o[k + 1] : 0ull;
            u64 sl = (o[k] << 1) | (prev >> 63);
            u64 sr = (o[k] >> 1) | (nxt << 63);
            sd[xx][yy][k] = o[k] | sl | sr;
        }
    }
    __syncthreads();

    // ---- phase 3: erosion for 16x16 core (zero-pad: borders -> 0) ----
    {
        int xx = t / TS;        // 0..15
        int yy = t - xx * TS;
        int ax = X0 + xx;
        int ay = Y0 + yy;
        if (ax == 0 || ax == G - 1 || ay == 0 || ay == G - 1) {
#pragma unroll
            for (int k = 0; k < WORDS; k++) se[xx][yy][k] = 0ull;
        } else {
            u64 a[WORDS];
#pragma unroll
            for (int k = 0; k < WORDS; k++) a[k] = ~0ull;
#pragma unroll
            for (int dx = 0; dx < 3; dx++)
#pragma unroll
                for (int dy = 0; dy < 3; dy++) {
#pragma unroll
                    for (int k = 0; k < WORDS; k++) a[k] &= sd[xx + dx][yy + dy][k];
                }
#pragma unroll
            for (int k = 0; k < WORDS; k++) {
                u64 prev = (k > 0)         ? a[k - 1] : 0ull;
                u64 nxt  = (k < WORDS - 1) ? a[k + 1] : 0ull;
                u64 sl = (a[k] << 1) | (prev >> 63);
                u64 sr = (a[k] >> 1) | (nxt << 63);
                se[xx][yy][k] = a[k] & sl & sr;
            }
        }
    }
    __syncthreads();

    // ---- phase 4: expand to fp32, coalesced float4 streaming stores ----
    const unsigned int* se32 = (const unsigned int*)se;  // [line][12] u32 words
    float4* __restrict__ out4 = (float4*)out;
#pragma unroll 4
    for (int it = 0; it < (TS * TS * (G / 4)) / 256; it++) {
        int flat = t + it * 256;           // [line_local (0..255)][q (0..95)]
        int ll = flat / (G / 4);
        int q  = flat - ll * (G / 4);
        unsigned int w = se32[ll * (WORDS * 2) + (q >> 3)];
        int sh = (q & 7) * 4;
        float4 v;
        v.x = (float)((w >> (sh + 0)) & 1u);
        v.y = (float)((w >> (sh + 1)) & 1u);
        v.z = (float)((w >> (sh + 2)) & 1u);
        v.w = (float)((w >> (sh + 3)) & 1u);
        int xx = ll / TS;
        int yy = ll - xx * TS;
        int line = (X0 + xx) * G + (Y0 + yy);
        __stcs(&out4[line * (G / 4) + q], v);
    }
}

// ---------------------------------------------------------------------------
// launch
// ---------------------------------------------------------------------------
extern "C" void kernel_launch(void* const* d_in, const int* in_sizes, int n_in,
                              void* d_out, int out_size) {
    const float* pts = (const float*)d_in[0];
    int n = in_sizes[0] / 3;
    float* out = (float*)d_out;

    // gaussian weights (fp32, numpy semantics): [e^-8, e^-2, 1, e^-2, e^-8]/sum
    float e8 = (float)exp(-8.0);
    float e2 = (float)exp(-2.0);
    float s = e8;
    s = s + e2;
    s = s + 1.0f;
    s = s + e2;
    s = s + e8;
    float w0 = e8 / s;
    float w1 = e2 / s;
    float w2 = 1.0f / s;

    clear_bits_kernel<<<(NLINES * WORDS + 511) / 512, 512>>>();
    smooth_scatter_kernel<<<(n + 255) / 256, 256>>>(pts, n, w0, w1, w2);
    dim3 grid(NT, NT);
    close_expand_kernel<<<grid, 256>>>(out);
}

// round 10
// speedup vs baseline: 3.8723x; 1.0187x over previous
#include <cuda_runtime.h>
#include <math.h>

#define G 384
#define WORDS 6            // 384 bits / 64
#define NLINES (G * G)     // (x,y) lines
#define TS 16              // tile size (output lines per axis per block)
#define NT (G / TS)        // 24 tiles per axis

typedef unsigned long long u64;

// bit-packed occupancy grid (7 MB; L2-resident)
__device__ u64 g_bits[NLINES * WORDS];

// ---------------------------------------------------------------------------
// K0: clear the bit grid. 16B stores, 2 per thread, few blocks.
// total 16B words = NLINES*WORDS/2 = 442368 = 432 blocks * 512 thr * 2
// ---------------------------------------------------------------------------
__global__ void clear_bits_kernel() {
    ulonglong2* p = reinterpret_cast<ulonglong2*>(g_bits);
    int i = blockIdx.x * (512 * 2) + threadIdx.x;
    ulonglong2 z = make_ulonglong2(0ull, 0ull);
    p[i] = z;
    p[i + 512] = z;
}

// ---------------------------------------------------------------------------
// K1: gaussian smooth (eager-XLA semantics: plain fp32 mul/add, each op
//     rounded; no FMA contraction) + scatter bits.
//     Index: XLA rewrites x / const -> x * (1/const); fl32(1/fl32(1/384))
//     is exactly 384.0f, so the reference scales by multiplication.
// ---------------------------------------------------------------------------
__device__ __forceinline__ int reflect_idx(int j, int n) {
    // numpy 'symmetric' padding: -1->0, -2->1, n->n-1, n+1->n-2
    if (j < 0)  return -j - 1;
    if (j >= n) return 2 * n - 1 - j;
    return j;
}

// 5-term chain, left-associated, every op individually rounded (no FMA)
__device__ __forceinline__ float chain5(float u0, float t0, float u1, float t1,
                                        float u2, float t2, float u3, float t3,
                                        float u4, float t4) {
    float s = __fmul_rn(u0, t0);
    s = __fadd_rn(s, __fmul_rn(u1, t1));
    s = __fadd_rn(s, __fmul_rn(u2, t2));
    s = __fadd_rn(s, __fmul_rn(u3, t3));
    s = __fadd_rn(s, __fmul_rn(u4, t4));
    return s;
}

__global__ void smooth_scatter_kernel(const float* __restrict__ pts, int n,
                                      float w0, float w1, float w2) {
    int j = blockIdx.x * blockDim.x + threadIdx.x;
    if (j >= n) return;

    int jm2 = reflect_idx(j - 2, n);
    int jm1 = reflect_idx(j - 1, n);
    int jp1 = reflect_idx(j + 1, n);
    int jp2 = reflect_idx(j + 2, n);

    float y[3];
#pragma unroll
    for (int c = 0; c < 3; c++) {
        float a = __ldg(&pts[jm2 * 3 + c]);
        float b = __ldg(&pts[jm1 * 3 + c]);
        float d = __ldg(&pts[j   * 3 + c]);
        float e = __ldg(&pts[jp1 * 3 + c]);
        float f = __ldg(&pts[jp2 * 3 + c]);
        y[c] = chain5(w0, a, w1, b, w2, d, w1, e, w0, f);
    }

    // axis-1 smoothing, symmetric pad of [y0,y1,y2] -> [y1,y0 | y0,y1,y2 | y2,y1]
    float z0 = chain5(w0, y[1], w1, y[0], w2, y[0], w1, y[1], w0, y[2]);
    float z1 = chain5(w0, y[0], w1, y[0], w2, y[1], w1, y[2], w0, y[2]);
    float z2 = chain5(w0, y[0], w1, y[1], w2, y[2], w1, y[2], w0, y[1]);

    int ix = (int)floorf(__fmul_rn(z0, 384.0f));
    int iy = (int)floorf(__fmul_rn(z1, 384.0f));
    int iz = (int)floorf(__fmul_rn(z2, 384.0f));
    ix = min(max(ix, 0), G - 1);
    iy = min(max(iy, 0), G - 1);
    iz = min(max(iz, 0), G - 1);

    atomicOr(&g_bits[(ix * G + iy) * WORDS + (iz >> 6)], 1ull << (iz & 63));
}

// ---------------------------------------------------------------------------
// K2: fused 3x3x3 closing (dilate -> erode) + fp32 expand, tiled in smem.
// Per block: 16x16 output lines. Halo: bits 20x20, dilated 18x18.
// OR/AND commute with the z bit-shifts, so each stage is:
//   combine 9 neighbor lines wordwise, then one z-shift triple.
// ---------------------------------------------------------------------------
__global__ void __launch_bounds__(256) close_expand_kernel(float* __restrict__ out) {
    __shared__ u64 sb[20][20][WORDS];   // bits halo      (19200 B)
    __shared__ u64 sd[18][18][WORDS];   // dilated        (15552 B)
    __shared__ u64 se[TS][TS][WORDS];   // eroded         (12288 B)

    int t = threadIdx.x;
    int X0 = (int)blockIdx.x * TS;      // tile origin x
    int Y0 = (int)blockIdx.y * TS;      // tile origin y

    // ---- phase 1: load 20x20 line halo of g_bits (zero OOB) ----
    for (int w = t; w < 20 * 20 * WORDS; w += 256) {
        int l  = w / WORDS;
        int k  = w - l * WORDS;
        int xx = l / 20;
        int yy = l - xx * 20;
        int ax = X0 - 2 + xx;
        int ay = Y0 - 2 + yy;
        u64 v = 0ull;
        if (ax >= 0 && ax < G && ay >= 0 && ay < G)
            v = g_bits[(ax * G + ay) * WORDS + k];
        sb[xx][yy][k] = v;
    }
    __syncthreads();

    // ---- phase 2: dilation for 18x18 interior ----
    for (int li = t; li < 18 * 18; li += 256) {
        int xx = li / 18;
        int yy = li - xx * 18;
        u64 o[WORDS];
#pragma unroll
        for (int k = 0; k < WORDS; k++) o[k] = 0ull;
#pragma unroll
        for (int dx = 0; dx < 3; dx++)
#pragma unroll
            for (int dy = 0; dy < 3; dy++) {
#pragma unroll
                for (int k = 0; k < WORDS; k++) o[k] |= sb[xx + dx][yy + dy][k];
            }
#pragma unroll
        for (int k = 0; k < WORDS; k++) {
            u64 prev = (k > 0)         ? o[k - 1] : 0ull;
            u64 nxt  = (k < WORDS - 1) ? o[k + 1] : 0ull;
            u64 sl = (o[k] << 1) | (prev >> 63);
            u64 sr = (o[k] >> 1) | (nxt << 63);
            sd[xx][yy][k] = o[k] | sl | sr;
        }
    }
    __syncthreads();

    // ---- phase 3: erosion for 16x16 core (zero-pad: borders -> 0) ----
    {
        int xx = t / TS;        // 0..15
        int yy = t - xx * TS;
        int ax = X0 + xx;
        int ay = Y0 + yy;
        if (ax == 0 || ax == G - 1 || ay == 0 || ay == G - 1) {
#pragma unroll
            for (int k = 0; k < WORDS; k++) se[xx][yy][k] = 0ull;
        } else {
            u64 a[WORDS];
#pragma unroll
            for (int k = 0; k < WORDS; k++) a[k] = ~0ull;
#pragma unroll
            for (int dx = 0; dx < 3; dx++)
#pragma unroll
                for (int dy = 0; dy < 3; dy++) {
#pragma unroll
                    for (int k = 0; k < WORDS; k++) a[k] &= sd[xx + dx][yy + dy][k];
                }
#pragma unroll
            for (int k = 0; k < WORDS; k++) {
                u64 prev = (k > 0)         ? a[k - 1] : 0ull;
                u64 nxt  = (k < WORDS - 1) ? a[k + 1] : 0ull;
                u64 sl = (a[k] << 1) | (prev >> 63);
                u64 sr = (a[k] >> 1) | (nxt << 63);
                se[xx][yy][k] = a[k] & sl & sr;
            }
        }
    }
    __syncthreads();

    // ---- phase 4: expand to fp32, coalesced uint4 streaming stores.
    // 0.0f/1.0f synthesized integerly: bit * 0x3F800000 (one IMAD, no I2F).
    const unsigned int* se32 = (const unsigned int*)se;  // [line][12] u32 words
    uint4* __restrict__ out4 = (uint4*)out;
#pragma unroll 4
    for (int it = 0; it < (TS * TS * (G / 4)) / 256; it++) {
        int flat = t + it * 256;           // [line_local (0..255)][q (0..95)]
        int ll = flat / (G / 4);
        int q  = flat - ll * (G / 4);
        unsigned int w = se32[ll * (WORDS * 2) + (q >> 3)];
        int sh = (q & 7) * 4;
        uint4 v;
        v.x = ((w >> (sh + 0)) & 1u) * 0x3F800000u;
        v.y = ((w >> (sh + 1)) & 1u) * 0x3F800000u;
        v.z = ((w >> (sh + 2)) & 1u) * 0x3F800000u;
        v.w = ((w >> (sh + 3)) & 1u) * 0x3F800000u;
        int xx = ll / TS;
        int yy = ll - xx * TS;
        int line = (X0 + xx) * G + (Y0 + yy);
        __stcs(&out4[line * (G / 4) + q], v);
    }
}

// ---------------------------------------------------------------------------
// launch
// ---------------------------------------------------------------------------
extern "C" void kernel_launch(void* const* d_in, const int* in_sizes, int n_in,
                              void* d_out, int out_size) {
    const float* pts = (const float*)d_in[0];
    int n = in_sizes[0] / 3;
    float* out = (float*)d_out;

    // gaussian weights (fp32, numpy semantics): [e^-8, e^-2, 1, e^-2, e^-8]/sum
    float e8 = (float)exp(-8.0);
    float e2 = (float)exp(-2.0);
    float s = e8;
    s = s + e2;
    s = s + 1.0f;
    s = s + e2;
    s = s + e8;
    float w0 = e8 / s;
    float w1 = e2 / s;
    float w2 = 1.0f / s;

    clear_bits_kernel<<<432, 512>>>();
    smooth_scatter_kernel<<<(n + 255) / 256, 256>>>(pts, n, w0, w1, w2);
    dim3 grid(NT, NT);
    close_expand_kernel<<<grid, 256>>>(out);
}